// round 13
// baseline (speedup 1.0000x reference)
#include <cuda_runtime.h>
#include <cuda_bf16.h>
#include <mma.h>
#include <cstdint>

using namespace nvcuda;

#define TT 128
#define BB 256
#define DG 512
#define DH 1024
#define LN_EPS 1e-5f

#define BK 32
#define APITCH 40                 // smem row pitch in bf16 elements (80 B)
#define NSPLIT 4
#define KS (DH / NSPLIT)          // 256
#define CHUNK_T 16                // zg timesteps per chunk
#define NCHUNK (TT / CHUNK_T)     // 8

// ---------------------------------------------------------------------------
// Device scratch (referenced ONLY from device code — never passed from host)
// ---------------------------------------------------------------------------
__device__ __align__(256) __nv_bfloat16 g_zhi[TT * BB * DG];
__device__ __align__(256) __nv_bfloat16 g_zlo[TT * BB * DG];
__device__ __align__(256) __nv_bfloat16 g_whh_hi[DH * DH];
__device__ __align__(256) __nv_bfloat16 g_whh_lo[DH * DH];
__device__ __align__(256) __nv_bfloat16 g_wg_hi[DH * DG];
__device__ __align__(256) __nv_bfloat16 g_wg_lo[DH * DG];
__device__ __align__(256) __nv_bfloat16 g_hhi[BB * DH];
__device__ __align__(256) __nv_bfloat16 g_hlo[BB * DH];
__device__ __align__(256) float g_partials[NSPLIT * BB * DH];

// ---------------------------------------------------------------------------
// PTX helpers (family-portable)
// ---------------------------------------------------------------------------
__device__ __forceinline__ void cp16(uint32_t s, const void* g) {
    asm volatile("cp.async.cg.shared.global [%0], [%1], 16;" :: "r"(s), "l"(g));
}
__device__ __forceinline__ void cp_commit() {
    asm volatile("cp.async.commit_group;" ::: "memory");
}
template<int N>
__device__ __forceinline__ void cp_wait() {
    asm volatile("cp.async.wait_group %0;" :: "n"(N) : "memory");
}
__device__ __forceinline__ void gdc_wait() {
    asm volatile("griddepcontrol.wait;" ::: "memory");
}
__device__ __forceinline__ void gdc_launch() {
    asm volatile("griddepcontrol.launch_dependents;" ::: "memory");
}

// ---------------------------------------------------------------------------
// fp32 -> bf16 hi/lo split kernels. TARGET: 0=z, 1=W_h, 2=W_g
// ---------------------------------------------------------------------------
template<int TARGET>
__global__ __launch_bounds__(256) void split_kernel(const float* __restrict__ src, int n4) {
    int i = blockIdx.x * 256 + threadIdx.x;
    if (i >= n4) return;
    __nv_bfloat16* hi;
    __nv_bfloat16* lo;
    if (TARGET == 0) { hi = g_zhi;    lo = g_zlo; }
    if (TARGET == 1) { hi = g_whh_hi; lo = g_whh_lo; }
    if (TARGET == 2) { hi = g_wg_hi;  lo = g_wg_lo; }
    float4 v = ((const float4*)src)[i];
    __nv_bfloat16 h0 = __float2bfloat16(v.x);
    __nv_bfloat16 h1 = __float2bfloat16(v.y);
    __nv_bfloat16 h2 = __float2bfloat16(v.z);
    __nv_bfloat16 h3 = __float2bfloat16(v.w);
    __nv_bfloat162 p;
    p.x = h0; p.y = h1; ((__nv_bfloat162*)hi)[i * 2]     = p;
    p.x = h2; p.y = h3; ((__nv_bfloat162*)hi)[i * 2 + 1] = p;
    p.x = __float2bfloat16(v.x - __bfloat162float(h0));
    p.y = __float2bfloat16(v.y - __bfloat162float(h1));
    ((__nv_bfloat162*)lo)[i * 2] = p;
    p.x = __float2bfloat16(v.z - __bfloat162float(h2));
    p.y = __float2bfloat16(v.w - __bfloat162float(h3));
    ((__nv_bfloat162*)lo)[i * 2 + 1] = p;
}

// ---------------------------------------------------------------------------
// zg projection GEMM (chunked): out[rows mbase..mbase+4096) = z @ W_g^T.
// CTA tile 128x128, 8 warps (2m x 4n), warp tile 64x32 (4x2 frags), BK=32.
// grid (8, 32) per chunk of 16 timesteps.
// ---------------------------------------------------------------------------
__global__ __launch_bounds__(256) void zg_gemm(float* __restrict__ Cout, int mbase)
{
    constexpr int ZA_HI = 0;
    constexpr int ZA_LO = 10240;
    constexpr int ZB_HI = 20480;
    constexpr int ZB_LO = 30720;
    constexpr int ZSTAGE = 40960;

    extern __shared__ char smem[];
    gdc_wait();
    const uint32_t sb = (uint32_t)__cvta_generic_to_shared(smem);
    const int tid = threadIdx.x;
    const int wid = tid >> 5;
    const int wm = wid & 1;
    const int wn = wid >> 1;
    const int n0 = blockIdx.x * 128;
    const int m0 = mbase + blockIdx.y * 128;
    constexpr int K = DG;
    constexpr int NIT = DG / BK;      // 16

    const int lr = tid >> 2;
    const int lc = tid & 3;

    wmma::fragment<wmma::accumulator, 16, 16, 16, float> acc[4][2];
    #pragma unroll
    for (int f = 0; f < 4; f++)
        #pragma unroll
        for (int n = 0; n < 2; n++)
            wmma::fill_fragment(acc[f][n], 0.0f);

    auto issue = [&](int it, int buf) {
        const int koff = it * BK;
        const uint32_t st = sb + buf * ZSTAGE;
        const uint32_t ro0 = (uint32_t)(lr * 80 + lc * 16);
        const uint32_t ro1 = (uint32_t)((lr + 64) * 80 + lc * 16);
        const size_t ga0 = (size_t)(m0 + lr) * K + koff + lc * 8;
        const size_t ga1 = (size_t)(m0 + lr + 64) * K + koff + lc * 8;
        cp16(st + ZA_HI + ro0, g_zhi + ga0);
        cp16(st + ZA_HI + ro1, g_zhi + ga1);
        cp16(st + ZA_LO + ro0, g_zlo + ga0);
        cp16(st + ZA_LO + ro1, g_zlo + ga1);
        const size_t gb0 = (size_t)(n0 + lr) * K + koff + lc * 8;
        const size_t gb1 = (size_t)(n0 + lr + 64) * K + koff + lc * 8;
        cp16(st + ZB_HI + ro0, g_wg_hi + gb0);
        cp16(st + ZB_HI + ro1, g_wg_hi + gb1);
        cp16(st + ZB_LO + ro0, g_wg_lo + gb0);
        cp16(st + ZB_LO + ro1, g_wg_lo + gb1);
        cp_commit();
    };

    issue(0, 0);
    for (int kt = 0; kt < NIT; kt++) {
        if (kt + 1 < NIT) { issue(kt + 1, (kt + 1) & 1); cp_wait<1>(); }
        else              { cp_wait<0>(); }
        __syncthreads();
        const char* stc = smem + (size_t)(kt & 1) * ZSTAGE;
        const __nv_bfloat16* sAh = (const __nv_bfloat16*)(stc + ZA_HI);
        const __nv_bfloat16* sAl = (const __nv_bfloat16*)(stc + ZA_LO);
        const __nv_bfloat16* sBh = (const __nv_bfloat16*)(stc + ZB_HI);
        const __nv_bfloat16* sBl = (const __nv_bfloat16*)(stc + ZB_LO);
        #pragma unroll
        for (int ks = 0; ks < 2; ks++) {
            wmma::fragment<wmma::matrix_a, 16, 16, 16, __nv_bfloat16, wmma::row_major> ah[4], al[4];
            wmma::fragment<wmma::matrix_b, 16, 16, 16, __nv_bfloat16, wmma::col_major> bh[2], bl[2];
            #pragma unroll
            for (int f = 0; f < 4; f++) {
                const int r = wm * 64 + f * 16;
                wmma::load_matrix_sync(ah[f], sAh + r * APITCH + ks * 16, APITCH);
                wmma::load_matrix_sync(al[f], sAl + r * APITCH + ks * 16, APITCH);
            }
            #pragma unroll
            for (int n = 0; n < 2; n++) {
                const int r = wn * 32 + n * 16;
                wmma::load_matrix_sync(bh[n], sBh + r * APITCH + ks * 16, APITCH);
                wmma::load_matrix_sync(bl[n], sBl + r * APITCH + ks * 16, APITCH);
            }
            #pragma unroll
            for (int f = 0; f < 4; f++)
                #pragma unroll
                for (int n = 0; n < 2; n++) {
                    wmma::mma_sync(acc[f][n], ah[f], bh[n], acc[f][n]);
                    wmma::mma_sync(acc[f][n], ah[f], bl[n], acc[f][n]);
                    wmma::mma_sync(acc[f][n], al[f], bh[n], acc[f][n]);
                }
        }
        __syncthreads();
    }

    #pragma unroll
    for (int f = 0; f < 4; f++) {
        const int row = m0 + wm * 64 + f * 16;
        #pragma unroll
        for (int n = 0; n < 2; n++) {
            const int col = n0 + wn * 32 + n * 16;
            wmma::store_matrix_sync(Cout + (size_t)row * DH + col, acc[f][n],
                                    DH, wmma::mem_row_major);
        }
    }
    gdc_launch();
}
#define ZG_SMEM (2 * 40960)

// ---------------------------------------------------------------------------
// Recurrent GEMM (round-6 proven config): split-K partials of h @ W_h^T.
// CTA 64x128, 8 warps (2m x 4n), warp 32x32 (2x2 frags), BK=32,
// double-buffered. grid (8 n, 4 m, 4 z) = 128 CTAs.
// ---------------------------------------------------------------------------
__global__ __launch_bounds__(256) void rec_gemm()
{
    constexpr int RA_HI = 0;
    constexpr int RA_LO = 5120;
    constexpr int RB_HI = 10240;
    constexpr int RB_LO = 20480;
    constexpr int RSTAGE = 30720;

    extern __shared__ char smem[];
    gdc_wait();                       // h_{t-1} must be fully written
    const uint32_t sb = (uint32_t)__cvta_generic_to_shared(smem);
    const int tid = threadIdx.x;
    const int wid = tid >> 5;
    const int wm = wid & 1;
    const int wn = wid >> 1;
    const int n0 = blockIdx.x * 128;
    const int m0 = blockIdx.y * 64;
    const int kb = blockIdx.z * KS;
    constexpr int NIT = KS / BK;      // 8

    const int lr = tid >> 2;
    const int lc = tid & 3;

    wmma::fragment<wmma::accumulator, 16, 16, 16, float> acc[2][2];
    #pragma unroll
    for (int f = 0; f < 2; f++)
        #pragma unroll
        for (int n = 0; n < 2; n++)
            wmma::fill_fragment(acc[f][n], 0.0f);

    auto issue = [&](int it, int buf) {
        const int koff = kb + it * BK;
        const uint32_t st = sb + buf * RSTAGE;
        const uint32_t ro = (uint32_t)(lr * 80 + lc * 16);
        const size_t ga = (size_t)(m0 + lr) * DH + koff + lc * 8;
        cp16(st + RA_HI + ro, g_hhi + ga);
        cp16(st + RA_LO + ro, g_hlo + ga);
        const size_t gb0 = (size_t)(n0 + lr) * DH + koff + lc * 8;
        const size_t gb1 = (size_t)(n0 + lr + 64) * DH + koff + lc * 8;
        const uint32_t ro1 = (uint32_t)((lr + 64) * 80 + lc * 16);
        cp16(st + RB_HI + ro,  g_whh_hi + gb0);
        cp16(st + RB_LO + ro,  g_whh_lo + gb0);
        cp16(st + RB_HI + ro1, g_whh_hi + gb1);
        cp16(st + RB_LO + ro1, g_whh_lo + gb1);
        cp_commit();
    };

    issue(0, 0);
    for (int kt = 0; kt < NIT; kt++) {
        if (kt + 1 < NIT) { issue(kt + 1, (kt + 1) & 1); cp_wait<1>(); }
        else              { cp_wait<0>(); }
        __syncthreads();
        const char* stc = smem + (size_t)(kt & 1) * RSTAGE;
        const __nv_bfloat16* sAh = (const __nv_bfloat16*)(stc + RA_HI);
        const __nv_bfloat16* sAl = (const __nv_bfloat16*)(stc + RA_LO);
        const __nv_bfloat16* sBh = (const __nv_bfloat16*)(stc + RB_HI);
        const __nv_bfloat16* sBl = (const __nv_bfloat16*)(stc + RB_LO);
        #pragma unroll
        for (int ks = 0; ks < 2; ks++) {
            wmma::fragment<wmma::matrix_a, 16, 16, 16, __nv_bfloat16, wmma::row_major> ah[2], al[2];
            wmma::fragment<wmma::matrix_b, 16, 16, 16, __nv_bfloat16, wmma::col_major> bh[2], bl[2];
            #pragma unroll
            for (int f = 0; f < 2; f++) {
                const int r = wm * 32 + f * 16;
                wmma::load_matrix_sync(ah[f], sAh + r * APITCH + ks * 16, APITCH);
                wmma::load_matrix_sync(al[f], sAl + r * APITCH + ks * 16, APITCH);
            }
            #pragma unroll
            for (int n = 0; n < 2; n++) {
                const int r = wn * 32 + n * 16;
                wmma::load_matrix_sync(bh[n], sBh + r * APITCH + ks * 16, APITCH);
                wmma::load_matrix_sync(bl[n], sBl + r * APITCH + ks * 16, APITCH);
            }
            #pragma unroll
            for (int f = 0; f < 2; f++)
                #pragma unroll
                for (int n = 0; n < 2; n++) {
                    wmma::mma_sync(acc[f][n], ah[f], bh[n], acc[f][n]);
                    wmma::mma_sync(acc[f][n], ah[f], bl[n], acc[f][n]);
                    wmma::mma_sync(acc[f][n], al[f], bh[n], acc[f][n]);
                }
        }
        __syncthreads();
    }

    float* Cp = g_partials + (size_t)blockIdx.z * (BB * DH);
    #pragma unroll
    for (int f = 0; f < 2; f++) {
        const int row = m0 + wm * 32 + f * 16;
        #pragma unroll
        for (int n = 0; n < 2; n++) {
            const int col = n0 + wn * 32 + n * 16;
            wmma::store_matrix_sync(Cp + (size_t)row * DH + col, acc[f][n],
                                    DH, wmma::mem_row_major);
        }
    }
    gdc_launch();
}
#define REC_SMEM (2 * 30720)

// ---------------------------------------------------------------------------
// LayerNorm + ReLU. pre = dst(=zg_t raw) + bias + sum_{s<NS} partials[s].
// Writes h fp32 to dst and bf16 hi/lo splits for the next step's GEMM.
// ---------------------------------------------------------------------------
template<int NS>
__global__ __launch_bounds__(256) void ln_kernel(
    float* __restrict__ dst, const float* __restrict__ bias,
    const float* __restrict__ gamma, const float* __restrict__ beta)
{
    gdc_wait();                       // partials (and zg) must be complete
    const int row = blockIdx.x;
    const int tid = threadIdx.x;
    const size_t base = (size_t)row * DH + tid * 4;
    float4 v = *(const float4*)(dst + base);
    {
        float4 bb = *(const float4*)(bias + tid * 4);
        v.x += bb.x; v.y += bb.y; v.z += bb.z; v.w += bb.w;
    }
    #pragma unroll
    for (int s = 0; s < NS; s++) {
        float4 p = *(const float4*)(g_partials + (size_t)s * (BB * DH) + base);
        v.x += p.x; v.y += p.y; v.z += p.z; v.w += p.w;
    }
    float s1 = v.x + v.y + v.z + v.w;
    float s2 = v.x * v.x + v.y * v.y + v.z * v.z + v.w * v.w;
    #pragma unroll
    for (int o = 16; o > 0; o >>= 1) {
        s1 += __shfl_xor_sync(0xffffffffu, s1, o);
        s2 += __shfl_xor_sync(0xffffffffu, s2, o);
    }
    __shared__ float r1[8], r2[8];
    const int wid = tid >> 5, lane = tid & 31;
    if (lane == 0) { r1[wid] = s1; r2[wid] = s2; }
    __syncthreads();
    if (wid == 0) {
        float a = (lane < 8) ? r1[lane] : 0.f;
        float b = (lane < 8) ? r2[lane] : 0.f;
        #pragma unroll
        for (int o = 4; o > 0; o >>= 1) {
            a += __shfl_xor_sync(0xffffffffu, a, o);
            b += __shfl_xor_sync(0xffffffffu, b, o);
        }
        if (lane == 0) { r1[0] = a; r2[0] = b; }
    }
    __syncthreads();
    const float mean = r1[0] * (1.0f / DH);
    const float var  = r2[0] * (1.0f / DH) - mean * mean;
    const float inv  = rsqrtf(var + LN_EPS);

    const float4 g = *(const float4*)(gamma + tid * 4);
    const float4 b = *(const float4*)(beta + tid * 4);
    float4 y;
    y.x = fmaxf((v.x - mean) * inv * g.x + b.x, 0.f);
    y.y = fmaxf((v.y - mean) * inv * g.y + b.y, 0.f);
    y.z = fmaxf((v.z - mean) * inv * g.z + b.z, 0.f);
    y.w = fmaxf((v.w - mean) * inv * g.w + b.w, 0.f);
    *(float4*)(dst + base) = y;

    __nv_bfloat16 h0 = __float2bfloat16(y.x);
    __nv_bfloat16 h1 = __float2bfloat16(y.y);
    __nv_bfloat16 h2 = __float2bfloat16(y.z);
    __nv_bfloat16 h3 = __float2bfloat16(y.w);
    __nv_bfloat162 p;
    p.x = h0; p.y = h1; *(__nv_bfloat162*)(g_hhi + base)     = p;
    p.x = h2; p.y = h3; *(__nv_bfloat162*)(g_hhi + base + 2) = p;
    p.x = __float2bfloat16(y.x - __bfloat162float(h0));
    p.y = __float2bfloat16(y.y - __bfloat162float(h1));
    *(__nv_bfloat162*)(g_hlo + base) = p;
    p.x = __float2bfloat16(y.z - __bfloat162float(h2));
    p.y = __float2bfloat16(y.w - __bfloat162float(h3));
    *(__nv_bfloat162*)(g_hlo + base + 2) = p;
    gdc_launch();
}

// ---------------------------------------------------------------------------
// PDL launch helper (main-stream chain)
// ---------------------------------------------------------------------------
template<typename F, typename... Args>
static inline void launch_pdl(F kern, dim3 grid, dim3 block, size_t smem, Args... args)
{
    cudaLaunchConfig_t cfg = {};
    cfg.gridDim = grid;
    cfg.blockDim = block;
    cfg.dynamicSmemBytes = smem;
    cfg.stream = 0;
    cudaLaunchAttribute attr[1];
    attr[0].id = cudaLaunchAttributeProgrammaticStreamSerialization;
    attr[0].val.programmaticStreamSerializationAllowed = 1;
    cfg.attrs = attr;
    cfg.numAttrs = 1;
    cudaLaunchKernelEx(&cfg, kern, args...);
}

// ---------------------------------------------------------------------------
// kernel_launch
// ---------------------------------------------------------------------------
extern "C" void kernel_launch(void* const* d_in, const int* in_sizes, int n_in,
                              void* d_out, int out_size)
{
    const float* z     = (const float*)d_in[0];   // [T,B,DG]
    const float* W_h   = (const float*)d_in[1];   // [DH,DH]
    const float* W_g   = (const float*)d_in[2];   // [DH,DG]
    const float* b_h   = (const float*)d_in[3];   // [DH]
    const float* gamma = (const float*)d_in[4];   // [DH]
    const float* beta  = (const float*)d_in[5];   // [DH]
    float* out = (float*)d_out;                   // [T,B,DH]

    // one-time host-side resources (streams/events; no device memory)
    static bool s_init = false;
    static cudaStream_t s2;
    static cudaEvent_t evFork;
    static cudaEvent_t evChunk[NCHUNK];
    if (!s_init) {
        int lo = 0, hi = 0;
        cudaDeviceGetStreamPriorityRange(&lo, &hi);
        cudaStreamCreateWithPriority(&s2, cudaStreamNonBlocking, lo);  // low prio
        cudaEventCreateWithFlags(&evFork, cudaEventDisableTiming);
        for (int k = 0; k < NCHUNK; k++)
            cudaEventCreateWithFlags(&evChunk[k], cudaEventDisableTiming);
        cudaFuncSetAttribute(zg_gemm,  cudaFuncAttributeMaxDynamicSharedMemorySize, ZG_SMEM);
        cudaFuncSetAttribute(rec_gemm, cudaFuncAttributeMaxDynamicSharedMemorySize, REC_SMEM);
        s_init = true;
    }

    // hi/lo bf16 splits (main stream)
    split_kernel<0><<<(TT * BB * DG / 4 + 255) / 256, 256>>>(z, TT * BB * DG / 4);
    split_kernel<1><<<(DH * DH / 4 + 255) / 256, 256>>>(W_h, DH * DH / 4);
    split_kernel<2><<<(DH * DG / 4 + 255) / 256, 256>>>(W_g, DH * DG / 4);

    // zg chunk 0 (t in [0,16)) serially on the main stream — LN_0 needs it now
    launch_pdl(zg_gemm, dim3(8, CHUNK_T * BB / 128), dim3(256), (size_t)ZG_SMEM, out, 0);

    // fork: remaining zg chunks on a low-priority side stream, overlapped with
    // the recurrence; per-chunk events gate the main chain at t = 16k.
    cudaEventRecord(evFork, 0);
    cudaStreamWaitEvent(s2, evFork, 0);
    for (int k = 1; k < NCHUNK; k++) {
        zg_gemm<<<dim3(8, CHUNK_T * BB / 128), 256, ZG_SMEM, s2>>>(
            out, k * CHUNK_T * BB);
        cudaEventRecord(evChunk[k], s2);
    }

    // t = 0: pre = zg_0 + bias (h0 = 0)
    launch_pdl(ln_kernel<0>, dim3(BB), dim3(256), (size_t)0, out, b_h, gamma, beta);

    // recurrence (PDL chain); join chunk k before its first consumer step
    for (int t = 1; t < TT; t++) {
        if ((t % CHUNK_T) == 0)
            cudaStreamWaitEvent(0, evChunk[t / CHUNK_T], 0);
        float* zg_t = out + (size_t)t * BB * DH;
        launch_pdl(rec_gemm, dim3(DH / 128, BB / 64, NSPLIT), dim3(256), (size_t)REC_SMEM);
        launch_pdl(ln_kernel<NSPLIT>, dim3(BB), dim3(256), (size_t)0, zg_t, b_h, gamma, beta);
    }
}

// round 17
// speedup vs baseline: 1.5927x; 1.5927x over previous
#include <cuda_runtime.h>
#include <cuda_bf16.h>
#include <mma.h>
#include <cstdint>

using namespace nvcuda;

#define TT 128
#define BB 256
#define DG 512
#define DH 1024
#define LN_EPS 1e-5f

#define BK 32
#define APITCH 40                 // smem row pitch in bf16 elements (80 B)
#define NSPLIT 4
#define KS (DH / NSPLIT)          // 256

// ---------------------------------------------------------------------------
// Device scratch (referenced ONLY from device code — never passed from host)
// ---------------------------------------------------------------------------
__device__ __align__(256) __nv_bfloat16 g_zhi[TT * BB * DG];
__device__ __align__(256) __nv_bfloat16 g_zlo[TT * BB * DG];
__device__ __align__(256) __nv_bfloat16 g_whh_hi[DH * DH];
__device__ __align__(256) __nv_bfloat16 g_whh_lo[DH * DH];
__device__ __align__(256) __nv_bfloat16 g_wg_hi[DH * DG];
__device__ __align__(256) __nv_bfloat16 g_wg_lo[DH * DG];
__device__ __align__(256) __nv_bfloat16 g_hhi[BB * DH];
__device__ __align__(256) __nv_bfloat16 g_hlo[BB * DH];
__device__ __align__(256) float g_partials[NSPLIT * BB * DH];

// ---------------------------------------------------------------------------
// PTX helpers (family-portable)
// ---------------------------------------------------------------------------
__device__ __forceinline__ void cp16(uint32_t s, const void* g) {
    asm volatile("cp.async.cg.shared.global [%0], [%1], 16;" :: "r"(s), "l"(g));
}
__device__ __forceinline__ void cp_commit() {
    asm volatile("cp.async.commit_group;" ::: "memory");
}
template<int N>
__device__ __forceinline__ void cp_wait() {
    asm volatile("cp.async.wait_group %0;" :: "n"(N) : "memory");
}
__device__ __forceinline__ void gdc_wait() {
    asm volatile("griddepcontrol.wait;" ::: "memory");
}
__device__ __forceinline__ void gdc_launch() {
    asm volatile("griddepcontrol.launch_dependents;" ::: "memory");
}

// ---------------------------------------------------------------------------
// Fused fp32 -> bf16 hi/lo split kernel: one launch covers z, W_h, W_g.
// Block ranges: [0, NB_Z) -> z, [NB_Z, NB_Z+NB_WH) -> W_h, rest -> W_g.
// ---------------------------------------------------------------------------
#define NB_Z  (TT * BB * DG / 4 / 256)        // 4096
#define NB_WH (DH * DH / 4 / 256)             // 1024
#define NB_WG (DH * DG / 4 / 256)             // 512

__global__ __launch_bounds__(256) void split_all(
    const float* __restrict__ z, const float* __restrict__ W_h,
    const float* __restrict__ W_g)
{
    const float* src;
    __nv_bfloat16* hi;
    __nv_bfloat16* lo;
    int i;
    if (blockIdx.x < NB_Z) {
        src = z;   hi = g_zhi;    lo = g_zlo;
        i = blockIdx.x * 256 + threadIdx.x;
    } else if (blockIdx.x < NB_Z + NB_WH) {
        src = W_h; hi = g_whh_hi; lo = g_whh_lo;
        i = (blockIdx.x - NB_Z) * 256 + threadIdx.x;
    } else {
        src = W_g; hi = g_wg_hi;  lo = g_wg_lo;
        i = (blockIdx.x - NB_Z - NB_WH) * 256 + threadIdx.x;
    }
    float4 v = ((const float4*)src)[i];
    __nv_bfloat16 h0 = __float2bfloat16(v.x);
    __nv_bfloat16 h1 = __float2bfloat16(v.y);
    __nv_bfloat16 h2 = __float2bfloat16(v.z);
    __nv_bfloat16 h3 = __float2bfloat16(v.w);
    __nv_bfloat162 p;
    p.x = h0; p.y = h1; ((__nv_bfloat162*)hi)[i * 2]     = p;
    p.x = h2; p.y = h3; ((__nv_bfloat162*)hi)[i * 2 + 1] = p;
    p.x = __float2bfloat16(v.x - __bfloat162float(h0));
    p.y = __float2bfloat16(v.y - __bfloat162float(h1));
    ((__nv_bfloat162*)lo)[i * 2] = p;
    p.x = __float2bfloat16(v.z - __bfloat162float(h2));
    p.y = __float2bfloat16(v.w - __bfloat162float(h3));
    ((__nv_bfloat162*)lo)[i * 2 + 1] = p;
    gdc_launch();
}

// ---------------------------------------------------------------------------
// zg projection GEMM (round-9 config, measured 310us): out = z @ W_g^T.
// CTA tile 128x128, 8 warps (2m x 4n), warp tile 64x32 (4x2 frags), BK=32,
// 2-stage double buffer (3-stage would halve its 2-CTA/SM occupancy).
// ---------------------------------------------------------------------------
__global__ __launch_bounds__(256) void zg_gemm(float* __restrict__ Cout)
{
    constexpr int ZA_HI = 0;
    constexpr int ZA_LO = 10240;
    constexpr int ZB_HI = 20480;
    constexpr int ZB_LO = 30720;
    constexpr int ZSTAGE = 40960;

    extern __shared__ char smem[];
    gdc_wait();
    const uint32_t sb = (uint32_t)__cvta_generic_to_shared(smem);
    const int tid = threadIdx.x;
    const int wid = tid >> 5;
    const int wm = wid & 1;
    const int wn = wid >> 1;
    const int n0 = blockIdx.x * 128;
    const int m0 = blockIdx.y * 128;
    constexpr int K = DG;
    constexpr int NIT = DG / BK;      // 16

    const int lr = tid >> 2;
    const int lc = tid & 3;

    wmma::fragment<wmma::accumulator, 16, 16, 16, float> acc[4][2];
    #pragma unroll
    for (int f = 0; f < 4; f++)
        #pragma unroll
        for (int n = 0; n < 2; n++)
            wmma::fill_fragment(acc[f][n], 0.0f);

    auto issue = [&](int it, int buf) {
        const int koff = it * BK;
        const uint32_t st = sb + buf * ZSTAGE;
        const uint32_t ro0 = (uint32_t)(lr * 80 + lc * 16);
        const uint32_t ro1 = (uint32_t)((lr + 64) * 80 + lc * 16);
        const size_t ga0 = (size_t)(m0 + lr) * K + koff + lc * 8;
        const size_t ga1 = (size_t)(m0 + lr + 64) * K + koff + lc * 8;
        cp16(st + ZA_HI + ro0, g_zhi + ga0);
        cp16(st + ZA_HI + ro1, g_zhi + ga1);
        cp16(st + ZA_LO + ro0, g_zlo + ga0);
        cp16(st + ZA_LO + ro1, g_zlo + ga1);
        const size_t gb0 = (size_t)(n0 + lr) * K + koff + lc * 8;
        const size_t gb1 = (size_t)(n0 + lr + 64) * K + koff + lc * 8;
        cp16(st + ZB_HI + ro0, g_wg_hi + gb0);
        cp16(st + ZB_HI + ro1, g_wg_hi + gb1);
        cp16(st + ZB_LO + ro0, g_wg_lo + gb0);
        cp16(st + ZB_LO + ro1, g_wg_lo + gb1);
        cp_commit();
    };

    issue(0, 0);
    for (int kt = 0; kt < NIT; kt++) {
        if (kt + 1 < NIT) { issue(kt + 1, (kt + 1) & 1); cp_wait<1>(); }
        else              { cp_wait<0>(); }
        __syncthreads();
        const char* stc = smem + (size_t)(kt & 1) * ZSTAGE;
        const __nv_bfloat16* sAh = (const __nv_bfloat16*)(stc + ZA_HI);
        const __nv_bfloat16* sAl = (const __nv_bfloat16*)(stc + ZA_LO);
        const __nv_bfloat16* sBh = (const __nv_bfloat16*)(stc + ZB_HI);
        const __nv_bfloat16* sBl = (const __nv_bfloat16*)(stc + ZB_LO);
        #pragma unroll
        for (int ks = 0; ks < 2; ks++) {
            wmma::fragment<wmma::matrix_a, 16, 16, 16, __nv_bfloat16, wmma::row_major> ah[4], al[4];
            wmma::fragment<wmma::matrix_b, 16, 16, 16, __nv_bfloat16, wmma::col_major> bh[2], bl[2];
            #pragma unroll
            for (int f = 0; f < 4; f++) {
                const int r = wm * 64 + f * 16;
                wmma::load_matrix_sync(ah[f], sAh + r * APITCH + ks * 16, APITCH);
                wmma::load_matrix_sync(al[f], sAl + r * APITCH + ks * 16, APITCH);
            }
            #pragma unroll
            for (int n = 0; n < 2; n++) {
                const int r = wn * 32 + n * 16;
                wmma::load_matrix_sync(bh[n], sBh + r * APITCH + ks * 16, APITCH);
                wmma::load_matrix_sync(bl[n], sBl + r * APITCH + ks * 16, APITCH);
            }
            #pragma unroll
            for (int f = 0; f < 4; f++)
                #pragma unroll
                for (int n = 0; n < 2; n++) {
                    wmma::mma_sync(acc[f][n], ah[f], bh[n], acc[f][n]);
                    wmma::mma_sync(acc[f][n], ah[f], bl[n], acc[f][n]);
                    wmma::mma_sync(acc[f][n], al[f], bh[n], acc[f][n]);
                }
        }
        __syncthreads();
    }

    #pragma unroll
    for (int f = 0; f < 4; f++) {
        const int row = m0 + wm * 64 + f * 16;
        #pragma unroll
        for (int n = 0; n < 2; n++) {
            const int col = n0 + wn * 32 + n * 16;
            wmma::store_matrix_sync(Cout + (size_t)row * DH + col, acc[f][n],
                                    DH, wmma::mem_row_major);
        }
    }
    gdc_launch();
}
#define ZG_SMEM (2 * 40960)

// ---------------------------------------------------------------------------
// Recurrent GEMM: split-K partials of h @ W_h^T.
// CTA 64x128, 8 warps (2m x 4n), warp 32x32 (2x2 frags), BK=32,
// *** 3-stage cp.async pipeline *** (issue depth 2 hides L2 latency at
// 1 CTA/SM). grid (8 n, 4 m, 4 z) = 128 CTAs.
// ---------------------------------------------------------------------------
__global__ __launch_bounds__(256) void rec_gemm()
{
    constexpr int RA_HI = 0;
    constexpr int RA_LO = 5120;
    constexpr int RB_HI = 10240;
    constexpr int RB_LO = 20480;
    constexpr int RSTAGE = 30720;

    extern __shared__ char smem[];
    gdc_wait();                       // h_{t-1} must be fully written
    const uint32_t sb = (uint32_t)__cvta_generic_to_shared(smem);
    const int tid = threadIdx.x;
    const int wid = tid >> 5;
    const int wm = wid & 1;
    const int wn = wid >> 1;
    const int n0 = blockIdx.x * 128;
    const int m0 = blockIdx.y * 64;
    const int kb = blockIdx.z * KS;
    constexpr int NIT = KS / BK;      // 8

    const int lr = tid >> 2;
    const int lc = tid & 3;

    wmma::fragment<wmma::accumulator, 16, 16, 16, float> acc[2][2];
    #pragma unroll
    for (int f = 0; f < 2; f++)
        #pragma unroll
        for (int n = 0; n < 2; n++)
            wmma::fill_fragment(acc[f][n], 0.0f);

    auto issue = [&](int it, int buf) {
        const int koff = kb + it * BK;
        const uint32_t st = sb + buf * RSTAGE;
        const uint32_t ro = (uint32_t)(lr * 80 + lc * 16);
        const size_t ga = (size_t)(m0 + lr) * DH + koff + lc * 8;
        cp16(st + RA_HI + ro, g_hhi + ga);
        cp16(st + RA_LO + ro, g_hlo + ga);
        const size_t gb0 = (size_t)(n0 + lr) * DH + koff + lc * 8;
        const size_t gb1 = (size_t)(n0 + lr + 64) * DH + koff + lc * 8;
        const uint32_t ro1 = (uint32_t)((lr + 64) * 80 + lc * 16);
        cp16(st + RB_HI + ro,  g_whh_hi + gb0);
        cp16(st + RB_LO + ro,  g_whh_lo + gb0);
        cp16(st + RB_HI + ro1, g_whh_hi + gb1);
        cp16(st + RB_LO + ro1, g_whh_lo + gb1);
        cp_commit();
    };

    // 3-stage prologue: two tiles in flight before the first wait
    issue(0, 0);
    issue(1, 1);
    for (int kt = 0; kt < NIT; kt++) {
        if (kt + 2 < NIT) { issue(kt + 2, (kt + 2) % 3); cp_wait<2>(); }
        else if (kt + 1 < NIT) { cp_wait<1>(); }
        else { cp_wait<0>(); }
        __syncthreads();
        const char* stc = smem + (size_t)(kt % 3) * RSTAGE;
        const __nv_bfloat16* sAh = (const __nv_bfloat16*)(stc + RA_HI);
        const __nv_bfloat16* sAl = (const __nv_bfloat16*)(stc + RA_LO);
        const __nv_bfloat16* sBh = (const __nv_bfloat16*)(stc + RB_HI);
        const __nv_bfloat16* sBl = (const __nv_bfloat16*)(stc + RB_LO);
        #pragma unroll
        for (int ks = 0; ks < 2; ks++) {
            wmma::fragment<wmma::matrix_a, 16, 16, 16, __nv_bfloat16, wmma::row_major> ah[2], al[2];
            wmma::fragment<wmma::matrix_b, 16, 16, 16, __nv_bfloat16, wmma::col_major> bh[2], bl[2];
            #pragma unroll
            for (int f = 0; f < 2; f++) {
                const int r = wm * 32 + f * 16;
                wmma::load_matrix_sync(ah[f], sAh + r * APITCH + ks * 16, APITCH);
                wmma::load_matrix_sync(al[f], sAl + r * APITCH + ks * 16, APITCH);
            }
            #pragma unroll
            for (int n = 0; n < 2; n++) {
                const int r = wn * 32 + n * 16;
                wmma::load_matrix_sync(bh[n], sBh + r * APITCH + ks * 16, APITCH);
                wmma::load_matrix_sync(bl[n], sBl + r * APITCH + ks * 16, APITCH);
            }
            #pragma unroll
            for (int f = 0; f < 2; f++)
                #pragma unroll
                for (int n = 0; n < 2; n++) {
                    wmma::mma_sync(acc[f][n], ah[f], bh[n], acc[f][n]);
                    wmma::mma_sync(acc[f][n], ah[f], bl[n], acc[f][n]);
                    wmma::mma_sync(acc[f][n], al[f], bh[n], acc[f][n]);
                }
        }
        __syncthreads();
    }

    float* Cp = g_partials + (size_t)blockIdx.z * (BB * DH);
    #pragma unroll
    for (int f = 0; f < 2; f++) {
        const int row = m0 + wm * 32 + f * 16;
        #pragma unroll
        for (int n = 0; n < 2; n++) {
            const int col = n0 + wn * 32 + n * 16;
            wmma::store_matrix_sync(Cp + (size_t)row * DH + col, acc[f][n],
                                    DH, wmma::mem_row_major);
        }
    }
    gdc_launch();
}
#define REC_SMEM (3 * 30720)

// ---------------------------------------------------------------------------
// LayerNorm + ReLU. pre = dst(=zg_t raw) + bias + sum_{s<NS} partials[s].
// Writes h fp32 to dst and bf16 hi/lo splits for the next step's GEMM.
// ---------------------------------------------------------------------------
template<int NS>
__global__ __launch_bounds__(256) void ln_kernel(
    float* __restrict__ dst, const float* __restrict__ bias,
    const float* __restrict__ gamma, const float* __restrict__ beta)
{
    gdc_wait();                       // partials (and zg) must be complete
    const int row = blockIdx.x;
    const int tid = threadIdx.x;
    const size_t base = (size_t)row * DH + tid * 4;
    float4 v = *(const float4*)(dst + base);
    {
        float4 bb = *(const float4*)(bias + tid * 4);
        v.x += bb.x; v.y += bb.y; v.z += bb.z; v.w += bb.w;
    }
    #pragma unroll
    for (int s = 0; s < NS; s++) {
        float4 p = *(const float4*)(g_partials + (size_t)s * (BB * DH) + base);
        v.x += p.x; v.y += p.y; v.z += p.z; v.w += p.w;
    }
    float s1 = v.x + v.y + v.z + v.w;
    float s2 = v.x * v.x + v.y * v.y + v.z * v.z + v.w * v.w;
    #pragma unroll
    for (int o = 16; o > 0; o >>= 1) {
        s1 += __shfl_xor_sync(0xffffffffu, s1, o);
        s2 += __shfl_xor_sync(0xffffffffu, s2, o);
    }
    __shared__ float r1[8], r2[8];
    const int wid = tid >> 5, lane = tid & 31;
    if (lane == 0) { r1[wid] = s1; r2[wid] = s2; }
    __syncthreads();
    if (wid == 0) {
        float a = (lane < 8) ? r1[lane] : 0.f;
        float b = (lane < 8) ? r2[lane] : 0.f;
        #pragma unroll
        for (int o = 4; o > 0; o >>= 1) {
            a += __shfl_xor_sync(0xffffffffu, a, o);
            b += __shfl_xor_sync(0xffffffffu, b, o);
        }
        if (lane == 0) { r1[0] = a; r2[0] = b; }
    }
    __syncthreads();
    const float mean = r1[0] * (1.0f / DH);
    const float var  = r2[0] * (1.0f / DH) - mean * mean;
    const float inv  = rsqrtf(var + LN_EPS);

    const float4 g = *(const float4*)(gamma + tid * 4);
    const float4 b = *(const float4*)(beta + tid * 4);
    float4 y;
    y.x = fmaxf((v.x - mean) * inv * g.x + b.x, 0.f);
    y.y = fmaxf((v.y - mean) * inv * g.y + b.y, 0.f);
    y.z = fmaxf((v.z - mean) * inv * g.z + b.z, 0.f);
    y.w = fmaxf((v.w - mean) * inv * g.w + b.w, 0.f);
    *(float4*)(dst + base) = y;

    __nv_bfloat16 h0 = __float2bfloat16(y.x);
    __nv_bfloat16 h1 = __float2bfloat16(y.y);
    __nv_bfloat16 h2 = __float2bfloat16(y.z);
    __nv_bfloat16 h3 = __float2bfloat16(y.w);
    __nv_bfloat162 p;
    p.x = h0; p.y = h1; *(__nv_bfloat162*)(g_hhi + base)     = p;
    p.x = h2; p.y = h3; *(__nv_bfloat162*)(g_hhi + base + 2) = p;
    p.x = __float2bfloat16(y.x - __bfloat162float(h0));
    p.y = __float2bfloat16(y.y - __bfloat162float(h1));
    *(__nv_bfloat162*)(g_hlo + base) = p;
    p.x = __float2bfloat16(y.z - __bfloat162float(h2));
    p.y = __float2bfloat16(y.w - __bfloat162float(h3));
    *(__nv_bfloat162*)(g_hlo + base + 2) = p;
    gdc_launch();
}

// ---------------------------------------------------------------------------
// PDL launch helper (main-stream chain)
// ---------------------------------------------------------------------------
template<typename F, typename... Args>
static inline void launch_pdl(F kern, dim3 grid, dim3 block, size_t smem, Args... args)
{
    cudaLaunchConfig_t cfg = {};
    cfg.gridDim = grid;
    cfg.blockDim = block;
    cfg.dynamicSmemBytes = smem;
    cfg.stream = 0;
    cudaLaunchAttribute attr[1];
    attr[0].id = cudaLaunchAttributeProgrammaticStreamSerialization;
    attr[0].val.programmaticStreamSerializationAllowed = 1;
    cfg.attrs = attr;
    cfg.numAttrs = 1;
    cudaLaunchKernelEx(&cfg, kern, args...);
}

// ---------------------------------------------------------------------------
// kernel_launch
// ---------------------------------------------------------------------------
extern "C" void kernel_launch(void* const* d_in, const int* in_sizes, int n_in,
                              void* d_out, int out_size)
{
    const float* z     = (const float*)d_in[0];   // [T,B,DG]
    const float* W_h   = (const float*)d_in[1];   // [DH,DH]
    const float* W_g   = (const float*)d_in[2];   // [DH,DG]
    const float* b_h   = (const float*)d_in[3];   // [DH]
    const float* gamma = (const float*)d_in[4];   // [DH]
    const float* beta  = (const float*)d_in[5];   // [DH]
    float* out = (float*)d_out;                   // [T,B,DH]

    cudaFuncSetAttribute(zg_gemm,  cudaFuncAttributeMaxDynamicSharedMemorySize, ZG_SMEM);
    cudaFuncSetAttribute(rec_gemm, cudaFuncAttributeMaxDynamicSharedMemorySize, REC_SMEM);

    // fused hi/lo bf16 splits (one launch for z, W_h, W_g)
    launch_pdl(split_all, dim3(NB_Z + NB_WH + NB_WG), dim3(256), (size_t)0,
               z, W_h, W_g);

    // zg(raw) = z @ W_g^T -> d_out; bias added in LN
    launch_pdl(zg_gemm, dim3(DH / 128, (TT * BB) / 128), dim3(256), (size_t)ZG_SMEM, out);

    // t = 0: pre = zg_0 + bias (h0 = 0)
    launch_pdl(ln_kernel<0>, dim3(BB), dim3(256), (size_t)0, out, b_h, gamma, beta);

    // recurrence: PDL chain hides launch latency between the 254 nodes
    for (int t = 1; t < TT; t++) {
        float* zg_t = out + (size_t)t * BB * DH;
        launch_pdl(rec_gemm, dim3(DH / 128, BB / 64, NSPLIT), dim3(256), (size_t)REC_SMEM);
        launch_pdl(ln_kernel<NSPLIT>, dim3(BB), dim3(256), (size_t)0, zg_t, b_h, gamma, beta);
    }
}